// round 3
// baseline (speedup 1.0000x reference)
#include <cuda_runtime.h>
#include <math.h>

#define BB 4
#define NN 4096
#define KK 16
#define NB 32          // 2k neighbors per query
#define TPB 512        // MLP block size (16 warps = 16 queries)

// ---------------- scratch (__device__ globals; no allocation allowed) -------
__device__ float g_feats[BB * NN * NB * 4];                 // {rx,ry,rz,dist} per token, 8MB
// folded params, flat layout:
//  W0 [4][64] (256) | C0 (64) | W1 [64][64] (4096) | C1 (64) | W2 [64][128] (8192) | C2 (128)
#define P_W0 0
#define P_C0 256
#define P_W1 (P_C0 + 64)
#define P_C1 (P_W1 + 4096)
#define P_W2 (P_C1 + 64)
#define P_C2 (P_W2 + 8192)
#define P_TOT (P_C2 + 128)     // 12800 floats
__device__ float g_params[P_TOT];

// ---------------- fold BN into conv weights --------------------------------
__global__ void fold_kernel(
    const float* __restrict__ w0, const float* __restrict__ b0, const float* __restrict__ ga0,
    const float* __restrict__ be0, const float* __restrict__ mm0, const float* __restrict__ vv0,
    const float* __restrict__ w1, const float* __restrict__ b1, const float* __restrict__ ga1,
    const float* __restrict__ be1, const float* __restrict__ mm1, const float* __restrict__ vv1,
    const float* __restrict__ w2, const float* __restrict__ b2, const float* __restrict__ ga2,
    const float* __restrict__ be2, const float* __restrict__ mm2, const float* __restrict__ vv2)
{
    int t = threadIdx.x;   // 128 threads
    for (int o = t; o < 64; o += 128) {
        float s = ga0[o] / sqrtf(vv0[o] + 1e-3f);
        g_params[P_C0 + o] = (b0[o] - mm0[o]) * s + be0[o];
        for (int c = 0; c < 4; c++) g_params[P_W0 + c * 64 + o] = w0[o * 4 + c] * s;
    }
    for (int o = t; o < 64; o += 128) {
        float s = ga1[o] / sqrtf(vv1[o] + 1e-3f);
        g_params[P_C1 + o] = (b1[o] - mm1[o]) * s + be1[o];
        for (int c = 0; c < 64; c++) g_params[P_W1 + c * 64 + o] = w1[o * 64 + c] * s;
    }
    for (int o = t; o < 128; o += 128) {
        float s = ga2[o] / sqrtf(vv2[o] + 1e-3f);
        g_params[P_C2 + o] = (b2[o] - mm2[o]) * s + be2[o];
        for (int c = 0; c < 64; c++) g_params[P_W2 + c * 128 + o] = w2[o * 64 + c] * s;
    }
}

// ---------------- brute-force kNN (top-16 per query per ref set) -----------
// grid: (NN/256, B, 2 sets), block 256. One thread = one query.
__global__ __launch_bounds__(256) void knn_kernel(
    const float* __restrict__ p1, const float* __restrict__ p2)
{
    const int tid = threadIdx.x;
    const int b = blockIdx.y;
    const int set = blockIdx.z;
    const int qi = blockIdx.x * 256 + tid;

    const float* qb = p1 + b * 3 * NN;
    const float* rb = (set == 0 ? p1 : p2) + b * 3 * NN;

    __shared__ float4 tile[512];              // {x,y,z,|r|^2}
    __shared__ float bd[KK * 256];            // sorted ascending distances [slot][tid]
    __shared__ int   bi[KK * 256];

    const float qx = qb[qi], qy = qb[NN + qi], qz = qb[2 * NN + qi];
    const float qq = qx * qx + qy * qy + qz * qz;

#pragma unroll
    for (int s = 0; s < KK; s++) bd[s * 256 + tid] = 3.4e38f;
    float worst = 3.4e38f;

    for (int t0 = 0; t0 < NN; t0 += 512) {
        __syncthreads();
        for (int j = tid; j < 512; j += 256) {
            int ci = t0 + j;
            float rx = rb[ci], ry = rb[NN + ci], rz = rb[2 * NN + ci];
            tile[j] = make_float4(rx, ry, rz, rx * rx + ry * ry + rz * rz);
        }
        __syncthreads();
#pragma unroll 4
        for (int j = 0; j < 512; j++) {
            float4 c = tile[j];
            float dot = qx * c.x + qy * c.y + qz * c.z;
            float d2 = qq - 2.0f * dot + c.w;     // same form as reference
            if (d2 < worst) {
                int p = KK - 1;
#pragma unroll 1
                while (p > 0 && bd[(p - 1) * 256 + tid] > d2) {
                    bd[p * 256 + tid] = bd[(p - 1) * 256 + tid];
                    bi[p * 256 + tid] = bi[(p - 1) * 256 + tid];
                    p--;
                }
                bd[p * 256 + tid] = d2;
                bi[p * 256 + tid] = t0 + j;
                worst = bd[(KK - 1) * 256 + tid];
            }
        }
    }

    // emit feats {resi, dist}; grouped nn is reconstructable as q + resi.
    float4* outp = (float4*)g_feats + ((size_t)(b * NN + qi) * NB + set * KK);
#pragma unroll 1
    for (int s = 0; s < KK; s++) {
        int ci = bi[s * 256 + tid];
        float rx = rb[ci] - qx, ry = rb[NN + ci] - qy, rz = rb[2 * NN + ci] - qz;
        float d2r = rx * rx + ry * ry + rz * rz;
        outp[s] = make_float4(rx, ry, rz, sqrtf(fmaxf(d2r, 1e-12f)));
    }
}

// ---------------- fused MLP + channel-max + softmax + weighted sum ---------
// warp = one query point, lane = one neighbor token.
// shared: folded weights (12800 f) + per-thread hidden column sbuf[64][TPB].
#define SMEM_FLOATS (P_TOT + 64 * TPB)
#define SMEM_BYTES  (SMEM_FLOATS * 4)

__global__ __launch_bounds__(TPB) void mlp_kernel(
    const float* __restrict__ p1, float* __restrict__ out)
{
    extern __shared__ float sm[];
    float* sW0  = sm + P_W0;
    float* sC0  = sm + P_C0;
    float* sW1  = sm + P_W1;
    float* sC1  = sm + P_C1;
    float* sW2  = sm + P_W2;
    float* sC2  = sm + P_C2;
    float* sbuf = sm + P_TOT;

    const int tid = threadIdx.x;
    for (int i = tid; i < P_TOT; i += TPB) sm[i] = g_params[i];
    __syncthreads();

    const int lane = tid & 31;
    const int wg = blockIdx.x * (TPB / 32) + (tid >> 5);   // = b*NN + n
    const int b = wg >> 12;
    const int n = wg & (NN - 1);

    const float4 f = ((const float4*)g_feats)[(size_t)wg * NB + lane];

    float acc[64];

    // ---- layer 0: 4 -> 64 ----
#pragma unroll
    for (int o = 0; o < 64; o++) acc[o] = sC0[o];
#pragma unroll
    for (int c = 0; c < 4; c++) {
        float xc = (c == 0) ? f.x : (c == 1) ? f.y : (c == 2) ? f.z : f.w;
        const float4* wp = (const float4*)(sW0 + c * 64);
#pragma unroll
        for (int o4 = 0; o4 < 16; o4++) {
            float4 w = wp[o4];
            acc[4 * o4 + 0] = fmaf(w.x, xc, acc[4 * o4 + 0]);
            acc[4 * o4 + 1] = fmaf(w.y, xc, acc[4 * o4 + 1]);
            acc[4 * o4 + 2] = fmaf(w.z, xc, acc[4 * o4 + 2]);
            acc[4 * o4 + 3] = fmaf(w.w, xc, acc[4 * o4 + 3]);
        }
    }
#pragma unroll
    for (int o = 0; o < 64; o++) sbuf[o * TPB + tid] = fmaxf(acc[o], 0.0f);

    // ---- layer 1: 64 -> 64 ----
#pragma unroll
    for (int o = 0; o < 64; o++) acc[o] = sC1[o];
#pragma unroll 2
    for (int c = 0; c < 64; c++) {
        float xc = sbuf[c * TPB + tid];
        const float4* wp = (const float4*)(sW1 + c * 64);
#pragma unroll
        for (int o4 = 0; o4 < 16; o4++) {
            float4 w = wp[o4];
            acc[4 * o4 + 0] = fmaf(w.x, xc, acc[4 * o4 + 0]);
            acc[4 * o4 + 1] = fmaf(w.y, xc, acc[4 * o4 + 1]);
            acc[4 * o4 + 2] = fmaf(w.z, xc, acc[4 * o4 + 2]);
            acc[4 * o4 + 3] = fmaf(w.w, xc, acc[4 * o4 + 3]);
        }
    }
#pragma unroll
    for (int o = 0; o < 64; o++) sbuf[o * TPB + tid] = fmaxf(acc[o], 0.0f);

    // ---- layer 2: 64 -> 128, fused relu + channel max ----
    float gmax = 0.0f;     // relu floor: max over relu(x) == max(0, max x)
#pragma unroll 1
    for (int h = 0; h < 2; h++) {
#pragma unroll
        for (int o = 0; o < 64; o++) acc[o] = sC2[h * 64 + o];
#pragma unroll 2
        for (int c = 0; c < 64; c++) {
            float xc = sbuf[c * TPB + tid];
            const float4* wp = (const float4*)(sW2 + c * 128 + h * 64);
#pragma unroll
            for (int o4 = 0; o4 < 16; o4++) {
                float4 w = wp[o4];
                acc[4 * o4 + 0] = fmaf(w.x, xc, acc[4 * o4 + 0]);
                acc[4 * o4 + 1] = fmaf(w.y, xc, acc[4 * o4 + 1]);
                acc[4 * o4 + 2] = fmaf(w.z, xc, acc[4 * o4 + 2]);
                acc[4 * o4 + 3] = fmaf(w.w, xc, acc[4 * o4 + 3]);
            }
        }
#pragma unroll
        for (int o = 0; o < 64; o++) gmax = fmaxf(gmax, acc[o]);
    }

    // ---- softmax over the 32 neighbors (one warp) ----
    float m = gmax;
#pragma unroll
    for (int off = 16; off; off >>= 1) m = fmaxf(m, __shfl_xor_sync(0xffffffffu, m, off));
    float e = expf(gmax - m);
    float ssum = e;
#pragma unroll
    for (int off = 16; off; off >>= 1) ssum += __shfl_xor_sync(0xffffffffu, ssum, off);
    float w = e / ssum;

    // out = sum_j w_j * nn_j = q + sum_j w_j * resi_j   (since sum w = 1)
    float wx = w * f.x, wy = w * f.y, wz = w * f.z;
#pragma unroll
    for (int off = 16; off; off >>= 1) {
        wx += __shfl_xor_sync(0xffffffffu, wx, off);
        wy += __shfl_xor_sync(0xffffffffu, wy, off);
        wz += __shfl_xor_sync(0xffffffffu, wz, off);
    }
    if (lane == 0) {
        const float* qb = p1 + b * 3 * NN;
        out[b * 3 * NN + n]          = qb[n]          + wx;
        out[b * 3 * NN + NN + n]     = qb[NN + n]     + wy;
        out[b * 3 * NN + 2 * NN + n] = qb[2 * NN + n] + wz;
    }
}

// ---------------- launch ---------------------------------------------------
extern "C" void kernel_launch(void* const* d_in, const int* in_sizes, int n_in,
                              void* d_out, int out_size)
{
    const float* p1 = (const float*)d_in[0];
    const float* p2 = (const float*)d_in[1];
    // d_in[2] = k (fixed at 16 for this shape)
    const float* w0 = (const float*)d_in[3];
    const float* b0 = (const float*)d_in[4];
    const float* g0 = (const float*)d_in[5];
    const float* e0 = (const float*)d_in[6];
    const float* m0 = (const float*)d_in[7];
    const float* v0 = (const float*)d_in[8];
    const float* w1 = (const float*)d_in[9];
    const float* b1 = (const float*)d_in[10];
    const float* g1 = (const float*)d_in[11];
    const float* e1 = (const float*)d_in[12];
    const float* m1 = (const float*)d_in[13];
    const float* v1 = (const float*)d_in[14];
    const float* w2 = (const float*)d_in[15];
    const float* b2 = (const float*)d_in[16];
    const float* g2 = (const float*)d_in[17];
    const float* e2 = (const float*)d_in[18];
    const float* m2 = (const float*)d_in[19];
    const float* v2 = (const float*)d_in[20];

    cudaFuncSetAttribute(mlp_kernel, cudaFuncAttributeMaxDynamicSharedMemorySize, SMEM_BYTES);

    fold_kernel<<<1, 128>>>(w0, b0, g0, e0, m0, v0,
                            w1, b1, g1, e1, m1, v1,
                            w2, b2, g2, e2, m2, v2);

    knn_kernel<<<dim3(NN / 256, BB, 2), 256>>>(p1, p2);

    const int nwarps = BB * NN;                 // 16384 queries
    mlp_kernel<<<nwarps / (TPB / 32), TPB, SMEM_BYTES>>>(p1, (float*)d_out);
}

// round 4
// speedup vs baseline: 4.0346x; 4.0346x over previous
#include <cuda_runtime.h>
#include <math.h>

#define BB 4
#define NN 4096
#define KK 16
#define NB 32          // 2k neighbors per query
#define TPB 512        // MLP block size (16 warps = 16 queries)
#define FULL 0xffffffffu

typedef unsigned long long u64;

// ---------------- scratch (__device__ globals; no allocation allowed) -------
__device__ float g_feats[BB * NN * NB * 4];                 // {rx,ry,rz,dist} per token, 8MB
// folded params, flat layout:
//  W0 [4][64] (256) | C0 (64) | W1 [64][64] (4096) | C1 (64) | W2 [64][128] (8192) | C2 (128)
#define P_W0 0
#define P_C0 256
#define P_W1 (P_C0 + 64)
#define P_C1 (P_W1 + 4096)
#define P_W2 (P_C1 + 64)
#define P_C2 (P_W2 + 8192)
#define P_TOT (P_C2 + 128)     // 12800 floats
__device__ float g_params[P_TOT];

// ---------------- f32x2 helpers --------------------------------------------
__device__ __forceinline__ u64 ffma2(u64 a, u64 b, u64 c) {
    u64 d;
    asm("fma.rn.f32x2 %0, %1, %2, %3;" : "=l"(d) : "l"(a), "l"(b), "l"(c));
    return d;
}
__device__ __forceinline__ u64 pack2(float x) {
    u64 r;
    unsigned xu = __float_as_uint(x);
    asm("mov.b64 %0, {%1, %1};" : "=l"(r) : "r"(xu));
    return r;
}
__device__ __forceinline__ void unpack2(u64 v, float& lo, float& hi) {
    unsigned a, b;
    asm("mov.b64 {%0, %1}, %2;" : "=r"(a), "=r"(b) : "l"(v));
    lo = __uint_as_float(a);
    hi = __uint_as_float(b);
}

// ---------------- fold BN into conv weights (parallel) ---------------------
__global__ void fold_kernel(
    const float* __restrict__ w0, const float* __restrict__ b0, const float* __restrict__ ga0,
    const float* __restrict__ be0, const float* __restrict__ mm0, const float* __restrict__ vv0,
    const float* __restrict__ w1, const float* __restrict__ b1, const float* __restrict__ ga1,
    const float* __restrict__ be1, const float* __restrict__ mm1, const float* __restrict__ vv1,
    const float* __restrict__ w2, const float* __restrict__ b2, const float* __restrict__ ga2,
    const float* __restrict__ be2, const float* __restrict__ mm2, const float* __restrict__ vv2)
{
    const int tid = threadIdx.x;   // 1024 threads, 1 block
    // layer0 weights: layout [c][64]
    for (int i = tid; i < 256; i += 1024) {
        int c = i >> 6, o = i & 63;
        float s = ga0[o] / sqrtf(vv0[o] + 1e-3f);
        g_params[P_W0 + c * 64 + o] = w0[o * 4 + c] * s;
    }
    for (int i = tid; i < 64; i += 1024) {
        float s = ga0[i] / sqrtf(vv0[i] + 1e-3f);
        g_params[P_C0 + i] = (b0[i] - mm0[i]) * s + be0[i];
    }
    // layer1 weights
    for (int i = tid; i < 4096; i += 1024) {
        int c = i >> 6, o = i & 63;
        float s = ga1[o] / sqrtf(vv1[o] + 1e-3f);
        g_params[P_W1 + c * 64 + o] = w1[o * 64 + c] * s;
    }
    for (int i = tid; i < 64; i += 1024) {
        float s = ga1[i] / sqrtf(vv1[i] + 1e-3f);
        g_params[P_C1 + i] = (b1[i] - mm1[i]) * s + be1[i];
    }
    // layer2 weights: layout [c][128]
    for (int i = tid; i < 8192; i += 1024) {
        int c = i >> 7, o = i & 127;
        float s = ga2[o] / sqrtf(vv2[o] + 1e-3f);
        g_params[P_W2 + c * 128 + o] = w2[o * 64 + c] * s;
    }
    for (int i = tid; i < 128; i += 1024) {
        float s = ga2[i] / sqrtf(vv2[i] + 1e-3f);
        g_params[P_C2 + i] = (b2[i] - mm2[i]) * s + be2[i];
    }
}

// ---------------- kNN: warp per query, warp-collective top-16 --------------
// Lane l (l<16) holds the l-th best (d2, idx), sorted ascending. Per step the
// 32 lanes evaluate 32 candidates; a warp-uniform threshold + ballot selects
// inserters; insertion is a branch-free shuffle shift. No divergence.
// grid: (NN/8, B, 2 sets), block 256 (8 warps = 8 queries). dyn smem: 64KB tile.
__global__ __launch_bounds__(256) void knn_kernel(
    const float* __restrict__ p1, const float* __restrict__ p2)
{
    extern __shared__ float4 tile[];       // 4096 x {x,y,z,|r|^2}
    const int lane = threadIdx.x & 31;
    const int warp = threadIdx.x >> 5;
    const int b = blockIdx.y;
    const int set = blockIdx.z;

    const float* qb = p1 + b * 3 * NN;
    const float* rb = (set == 0 ? p1 : p2) + b * 3 * NN;

    for (int j = threadIdx.x; j < NN; j += 256) {
        float rx = rb[j], ry = rb[NN + j], rz = rb[2 * NN + j];
        tile[j] = make_float4(rx, ry, rz, rx * rx + ry * ry + rz * rz);
    }
    __syncthreads();

    const int qi = blockIdx.x * 8 + warp;
    const float qx = qb[qi], qy = qb[NN + qi], qz = qb[2 * NN + qi];
    const float qq = qx * qx + qy * qy + qz * qz;

    float ld = 3.4e38f;     // this lane's slot distance (lanes 0..15 meaningful)
    int   li = 0;
    float thresh = 3.4e38f; // warp-uniform copy of slot-15 distance

#pragma unroll 2
    for (int t = 0; t < NN / 32; t++) {
        const int j = t * 32 + lane;
        float4 c = tile[j];
        float dot = qx * c.x + qy * c.y + qz * c.z;
        float d2 = fmaf(-2.0f, dot, qq) + c.w;      // same form as reference
        unsigned mask = __ballot_sync(FULL, d2 < thresh);
        if (mask) {
            do {
                int src = __ffs(mask) - 1;
                mask &= mask - 1;
                float xd = __shfl_sync(FULL, d2, src);
                int   xi = __shfl_sync(FULL, j, src);
                float pd = __shfl_up_sync(FULL, ld, 1);
                int   pi = __shfl_up_sync(FULL, li, 1);
                // stale-threshold candidates no-op naturally (take=false everywhere)
                bool take  = (xd < ld);
                bool shift = (lane > 0) && (xd < pd);
                ld = take ? (shift ? pd : xd) : ld;
                li = take ? (shift ? pi : xi) : li;
            } while (mask);
            thresh = __shfl_sync(FULL, ld, 15);
        }
    }

    if (lane < KK) {
        float4 c = tile[li];
        float rx = c.x - qx, ry = c.y - qy, rz = c.z - qz;
        float d2r = rx * rx + ry * ry + rz * rz;
        float dist = sqrtf(fmaxf(d2r, 1e-12f));
        ((float4*)g_feats)[((size_t)(b * NN + qi)) * NB + set * KK + lane] =
            make_float4(rx, ry, rz, dist);
    }
}

// ---------------- fused MLP (f32x2) + max + softmax + weighted sum ---------
// warp = one query point, lane = one neighbor token.
// Accumulators are packed f32x2 pairs of adjacent output channels.
#define SMEM_FLOATS (P_TOT + 64 * TPB)
#define SMEM_BYTES  (SMEM_FLOATS * 4)

__global__ __launch_bounds__(TPB) void mlp_kernel(
    const float* __restrict__ p1, float* __restrict__ out)
{
    extern __shared__ float sm[];
    float* sW0  = sm + P_W0;
    float* sW1  = sm + P_W1;
    float* sW2  = sm + P_W2;
    float* sbuf = sm + P_TOT;

    const int tid = threadIdx.x;
    for (int i = tid; i < P_TOT; i += TPB) sm[i] = g_params[i];
    __syncthreads();

    const int lane = tid & 31;
    const int wg = blockIdx.x * (TPB / 32) + (tid >> 5);   // = b*NN + n
    const int b = wg >> 12;
    const int n = wg & (NN - 1);

    const float4 f = ((const float4*)g_feats)[(size_t)wg * NB + lane];

    u64 acc[32];

    // ---- layer 0: 4 -> 64 ----
    {
        const u64* cb = (const u64*)(sm + P_C0);
#pragma unroll
        for (int p = 0; p < 32; p++) acc[p] = cb[p];
#pragma unroll
        for (int c = 0; c < 4; c++) {
            float xc = (c == 0) ? f.x : (c == 1) ? f.y : (c == 2) ? f.z : f.w;
            u64 xx = pack2(xc);
            const ulonglong2* wp = (const ulonglong2*)(sW0 + c * 64);
#pragma unroll
            for (int q = 0; q < 16; q++) {
                ulonglong2 w = wp[q];
                acc[2 * q + 0] = ffma2(w.x, xx, acc[2 * q + 0]);
                acc[2 * q + 1] = ffma2(w.y, xx, acc[2 * q + 1]);
            }
        }
#pragma unroll
        for (int p = 0; p < 32; p++) {
            float lo, hi; unpack2(acc[p], lo, hi);
            sbuf[(2 * p) * TPB + tid]     = fmaxf(lo, 0.0f);
            sbuf[(2 * p + 1) * TPB + tid] = fmaxf(hi, 0.0f);
        }
    }

    // ---- layer 1: 64 -> 64 ----
    {
        const u64* cb = (const u64*)(sm + P_C1);
#pragma unroll
        for (int p = 0; p < 32; p++) acc[p] = cb[p];
#pragma unroll 2
        for (int c = 0; c < 64; c++) {
            u64 xx = pack2(sbuf[c * TPB + tid]);
            const ulonglong2* wp = (const ulonglong2*)(sW1 + c * 64);
#pragma unroll
            for (int q = 0; q < 16; q++) {
                ulonglong2 w = wp[q];
                acc[2 * q + 0] = ffma2(w.x, xx, acc[2 * q + 0]);
                acc[2 * q + 1] = ffma2(w.y, xx, acc[2 * q + 1]);
            }
        }
#pragma unroll
        for (int p = 0; p < 32; p++) {
            float lo, hi; unpack2(acc[p], lo, hi);
            sbuf[(2 * p) * TPB + tid]     = fmaxf(lo, 0.0f);
            sbuf[(2 * p + 1) * TPB + tid] = fmaxf(hi, 0.0f);
        }
    }

    // ---- layer 2: 64 -> 128 (two halves), fused relu + channel max ----
    float gmax = 0.0f;     // relu floor: max over relu(x) == max(0, max x)
#pragma unroll 1
    for (int h = 0; h < 2; h++) {
        const u64* cb = (const u64*)(sm + P_C2) + h * 32;
#pragma unroll
        for (int p = 0; p < 32; p++) acc[p] = cb[p];
#pragma unroll 2
        for (int c = 0; c < 64; c++) {
            u64 xx = pack2(sbuf[c * TPB + tid]);
            const ulonglong2* wp = (const ulonglong2*)(sW2 + c * 128 + h * 64);
#pragma unroll
            for (int q = 0; q < 16; q++) {
                ulonglong2 w = wp[q];
                acc[2 * q + 0] = ffma2(w.x, xx, acc[2 * q + 0]);
                acc[2 * q + 1] = ffma2(w.y, xx, acc[2 * q + 1]);
            }
        }
#pragma unroll
        for (int p = 0; p < 32; p++) {
            float lo, hi; unpack2(acc[p], lo, hi);
            gmax = fmaxf(gmax, fmaxf(lo, hi));
        }
    }

    // ---- softmax over the 32 neighbors (one warp) ----
    float m = gmax;
#pragma unroll
    for (int off = 16; off; off >>= 1) m = fmaxf(m, __shfl_xor_sync(FULL, m, off));
    float e = expf(gmax - m);
    float ssum = e;
#pragma unroll
    for (int off = 16; off; off >>= 1) ssum += __shfl_xor_sync(FULL, ssum, off);
    float w = e / ssum;

    // out = sum_j w_j * nn_j = q + sum_j w_j * resi_j   (since sum w = 1)
    float wx = w * f.x, wy = w * f.y, wz = w * f.z;
#pragma unroll
    for (int off = 16; off; off >>= 1) {
        wx += __shfl_xor_sync(FULL, wx, off);
        wy += __shfl_xor_sync(FULL, wy, off);
        wz += __shfl_xor_sync(FULL, wz, off);
    }
    if (lane == 0) {
        const float* qb = p1 + b * 3 * NN;
        out[b * 3 * NN + n]          = qb[n]          + wx;
        out[b * 3 * NN + NN + n]     = qb[NN + n]     + wy;
        out[b * 3 * NN + 2 * NN + n] = qb[2 * NN + n] + wz;
    }
}

// ---------------- launch ---------------------------------------------------
extern "C" void kernel_launch(void* const* d_in, const int* in_sizes, int n_in,
                              void* d_out, int out_size)
{
    const float* p1 = (const float*)d_in[0];
    const float* p2 = (const float*)d_in[1];
    // d_in[2] = k (fixed at 16 for this shape)
    const float* w0 = (const float*)d_in[3];
    const float* b0 = (const float*)d_in[4];
    const float* g0 = (const float*)d_in[5];
    const float* e0 = (const float*)d_in[6];
    const float* m0 = (const float*)d_in[7];
    const float* v0 = (const float*)d_in[8];
    const float* w1 = (const float*)d_in[9];
    const float* b1 = (const float*)d_in[10];
    const float* g1 = (const float*)d_in[11];
    const float* e1 = (const float*)d_in[12];
    const float* m1 = (const float*)d_in[13];
    const float* v1 = (const float*)d_in[14];
    const float* w2 = (const float*)d_in[15];
    const float* b2 = (const float*)d_in[16];
    const float* g2 = (const float*)d_in[17];
    const float* e2 = (const float*)d_in[18];
    const float* m2 = (const float*)d_in[19];
    const float* v2 = (const float*)d_in[20];

    cudaFuncSetAttribute(mlp_kernel, cudaFuncAttributeMaxDynamicSharedMemorySize, SMEM_BYTES);
    cudaFuncSetAttribute(knn_kernel, cudaFuncAttributeMaxDynamicSharedMemorySize, NN * 16);

    fold_kernel<<<1, 1024>>>(w0, b0, g0, e0, m0, v0,
                             w1, b1, g1, e1, m1, v1,
                             w2, b2, g2, e2, m2, v2);

    knn_kernel<<<dim3(NN / 8, BB, 2), 256, NN * 16>>>(p1, p2);

    const int nwarps = BB * NN;                 // 16384 queries
    mlp_kernel<<<nwarps / (TPB / 32), TPB, SMEM_BYTES>>>(p1, (float*)d_out);
}